// round 4
// baseline (speedup 1.0000x reference)
#include <cuda_runtime.h>
#include <cstdint>

// PyramidROIAlign, two-phase:
//   Kernel 1: per-(roi, pool-point) bilinear params -> __device__ scratch.
//   Kernel 2: flat element-wise gather/lerp/store. One thread = one float4.
//
//   boxes: (2, 1000, 4) f32; p2..p5: (2, S, S, 256) f32 NHWC, S=256/128/64/32
//   out:   (2, 1000, 7, 7, 256) f32

#define BATCH   2
#define NROI    1000
#define POOLH   7
#define POOLW   7
#define NCH     256
#define NCH4    (NCH / 4)            // 64
#define POINTS  (POOLH * POOLW)      // 49
#define NPTS    (BATCH * NROI * POINTS)        // 98000
#define NELEM   (NPTS * NCH4)                  // 6,272,000 float4

struct alignas(16) PtParams {
    const float4* p00;
    const float4* p01;
    const float4* p10;
    const float4* p11;
    float wx, wy;
    float pad0, pad1;     // 48 bytes total, 16B-aligned
};

__device__ PtParams g_params[NPTS];   // 4.7 MB scratch

// ---------------------------------------------------------------- kernel 1
__global__ __launch_bounds__(256) void compute_params_kernel(
    const float* __restrict__ boxes,
    const float* __restrict__ p2,
    const float* __restrict__ p3,
    const float* __restrict__ p4,
    const float* __restrict__ p5)
{
    const int idx = blockIdx.x * blockDim.x + threadIdx.x;
    if (idx >= NPTS) return;

    const int roi = idx / POINTS;          // 0..1999
    const int pt  = idx - roi * POINTS;    // 0..48
    const int py  = pt / POOLW;
    const int px  = pt - py * POOLW;
    const int b   = roi >= NROI ? 1 : 0;

    const float4 bx = __ldg((const float4*)(boxes) + roi);
    const float y1 = bx.x, x1 = bx.y, y2 = bx.z, x2 = bx.w;
    const float h = y2 - y1;
    const float w = x2 - x1;

    // roi_level = clip(round(log2(sqrt(max(h*w,1e-12)) / (224/1024))), 2, 5)
    // rintf = round-half-to-even, matches jnp.round.
    const float lvlf = log2f(sqrtf(fmaxf(h * w, 1e-12f)) / 0.21875f);
    int level = (int)rintf(lvlf);
    level = min(max(level, 2), 5);

    const float* feat;
    int H;
    if (level == 2)      { feat = p2; H = 256; }
    else if (level == 3) { feat = p3; H = 128; }
    else if (level == 4) { feat = p4; H = 64;  }
    else                 { feat = p5; H = 32;  }

    const float Hm1 = (float)(H - 1);
    const float ty = (float)py * (1.0f / 6.0f);
    const float tx = (float)px * (1.0f / 6.0f);
    const float ysf = (y1 + h * ty) * Hm1;
    const float xsf = (x1 + w * tx) * Hm1;

    const float y0f = floorf(ysf);
    const float x0f = floorf(xsf);
    const float wy = ysf - y0f;   // weights from UNCLAMPED floor (matches ref)
    const float wx = xsf - x0f;

    const int y0  = min(max((int)y0f, 0), H - 1);
    const int y1i = min(max((int)y0f + 1, 0), H - 1);
    const int x0  = min(max((int)x0f, 0), H - 1);
    const int x1i = min(max((int)x0f + 1, 0), H - 1);

    // NHWC float4 view: feat4[((b*H + y)*H + x)*64 + c]
    const float4* f4 = (const float4*)feat;
    const int rowb0 = (b * H + y0)  * H;
    const int rowb1 = (b * H + y1i) * H;

    PtParams P;
    P.p00 = f4 + (rowb0 + x0 ) * NCH4;
    P.p01 = f4 + (rowb0 + x1i) * NCH4;
    P.p10 = f4 + (rowb1 + x0 ) * NCH4;
    P.p11 = f4 + (rowb1 + x1i) * NCH4;
    P.wx = wx;
    P.wy = wy;
    P.pad0 = 0.f; P.pad1 = 0.f;
    g_params[idx] = P;
}

// ---------------------------------------------------------------- kernel 2
__global__ __launch_bounds__(256, 8) void gather_lerp_kernel(
    float4* __restrict__ out)
{
    const int gid = blockIdx.x * blockDim.x + threadIdx.x;  // < 6,272,000

    const int pt = gid >> 6;        // global point index 0..97999
    const int c  = gid & 63;        // float4 channel

    // Warp-uniform param load (all 32 lanes same pt -> L1 broadcast).
    const PtParams P = g_params[pt];

    const float4 v00 = __ldg(P.p00 + c);
    const float4 v01 = __ldg(P.p01 + c);
    const float4 v10 = __ldg(P.p10 + c);
    const float4 v11 = __ldg(P.p11 + c);

    const float wx = P.wx, wy = P.wy;
    float4 r;
    {
        float t, bo;
        t  = v00.x + wx * (v01.x - v00.x);
        bo = v10.x + wx * (v11.x - v10.x);
        r.x = t + wy * (bo - t);
        t  = v00.y + wx * (v01.y - v00.y);
        bo = v10.y + wx * (v11.y - v10.y);
        r.y = t + wy * (bo - t);
        t  = v00.z + wx * (v01.z - v00.z);
        bo = v10.z + wx * (v11.z - v10.z);
        r.z = t + wy * (bo - t);
        t  = v00.w + wx * (v01.w - v00.w);
        bo = v10.w + wx * (v11.w - v10.w);
        r.w = t + wy * (bo - t);
    }

    // Streaming store: 100 MB write-once, keep L2 for feature reads.
    __stcs(out + gid, r);
}

extern "C" void kernel_launch(void* const* d_in, const int* in_sizes, int n_in,
                              void* d_out, int out_size)
{
    const float* boxes = (const float*)d_in[0];
    const float* p2    = (const float*)d_in[1];
    const float* p3    = (const float*)d_in[2];
    const float* p4    = (const float*)d_in[3];
    const float* p5    = (const float*)d_in[4];
    float4* out = (float4*)d_out;

    compute_params_kernel<<<(NPTS + 255) / 256, 256>>>(boxes, p2, p3, p4, p5);
    gather_lerp_kernel<<<NELEM / 256, 256>>>(out);   // 24500 blocks exactly
}

// round 5
// speedup vs baseline: 1.0107x; 1.0107x over previous
#include <cuda_runtime.h>
#include <cstdint>

// PyramidROIAlign, single kernel, warp-per-pool-point:
//   boxes: (2, 1000, 4) f32; p2..p5: (2, S, S, 256) f32 NHWC, S=256/128/64/32
//   out:   (2, 1000, 7, 7, 256) f32
//
// 98000 points = 12250 blocks x 8 warps (exact, no tail).
// Warp-uniform param math in registers (no smem, no sync, no scratch).
// Each lane: 8 batched independent LDG.128 (4 corners x 2 channel halves),
// 2 lerps, 2 streaming STG.128.

#define BATCH   2
#define NROI    1000
#define POOLH   7
#define POOLW   7
#define NCH     256
#define NCH4    (NCH / 4)            // 64
#define POINTS  (POOLH * POOLW)      // 49
#define NPTS    (BATCH * NROI * POINTS)   // 98000

__device__ __forceinline__ float4 lerp2(const float4 v00, const float4 v01,
                                        const float4 v10, const float4 v11,
                                        const float wx, const float wy)
{
    float4 r;
    float t, bo;
    t  = v00.x + wx * (v01.x - v00.x);
    bo = v10.x + wx * (v11.x - v10.x);
    r.x = t + wy * (bo - t);
    t  = v00.y + wx * (v01.y - v00.y);
    bo = v10.y + wx * (v11.y - v10.y);
    r.y = t + wy * (bo - t);
    t  = v00.z + wx * (v01.z - v00.z);
    bo = v10.z + wx * (v11.z - v10.z);
    r.z = t + wy * (bo - t);
    t  = v00.w + wx * (v01.w - v00.w);
    bo = v10.w + wx * (v11.w - v10.w);
    r.w = t + wy * (bo - t);
    return r;
}

__global__ __launch_bounds__(256) void pyramid_roi_align_kernel(
    const float* __restrict__ boxes,
    const float* __restrict__ p2,
    const float* __restrict__ p3,
    const float* __restrict__ p4,
    const float* __restrict__ p5,
    float4* __restrict__ out)
{
    const int lane = threadIdx.x & 31;
    const int wrp  = threadIdx.x >> 5;
    const int pt   = blockIdx.x * 8 + wrp;    // 0..97999, exact

    // ---- warp-uniform param computation (registers only) ----
    const int roi = pt / POINTS;              // 0..1999 (IMAD magic div)
    const int ppt = pt - roi * POINTS;        // 0..48
    const int py  = ppt / POOLW;
    const int px  = ppt - py * POOLW;
    const int b   = roi >= NROI ? 1 : 0;

    // boxes: 32KB, L1-resident after warmup -> short dependent hop.
    const float4 bx = __ldg((const float4*)(boxes) + roi);
    const float y1 = bx.x, x1 = bx.y, y2 = bx.z, x2 = bx.w;
    const float h = y2 - y1;
    const float w = x2 - x1;

    // roi_level = clip(round(log2(sqrt(max(h*w,1e-12)) / (224/1024))), 2, 5)
    // rintf = round-half-to-even, matches jnp.round.
    const float lvlf = log2f(sqrtf(fmaxf(h * w, 1e-12f)) / 0.21875f);
    int level = (int)rintf(lvlf);
    level = min(max(level, 2), 5);

    const float* feat;
    int H;
    if (level == 2)      { feat = p2; H = 256; }
    else if (level == 3) { feat = p3; H = 128; }
    else if (level == 4) { feat = p4; H = 64;  }
    else                 { feat = p5; H = 32;  }

    const float Hm1 = (float)(H - 1);
    const float ty = (float)py * (1.0f / 6.0f);
    const float tx = (float)px * (1.0f / 6.0f);
    const float ysf = (y1 + h * ty) * Hm1;
    const float xsf = (x1 + w * tx) * Hm1;

    const float y0f = floorf(ysf);
    const float x0f = floorf(xsf);
    const float wy = ysf - y0f;   // weights from UNCLAMPED floor (matches ref)
    const float wx = xsf - x0f;

    const int y0  = min(max((int)y0f, 0), H - 1);
    const int y1i = min(max((int)y0f + 1, 0), H - 1);
    const int x0  = min(max((int)x0f, 0), H - 1);
    const int x1i = min(max((int)x0f + 1, 0), H - 1);

    // NHWC float4 view: feat4[((b*H + y)*H + x)*64 + c]
    const float4* __restrict__ f4 = (const float4*)feat;
    const int rowb0 = (b * H + y0)  * H;
    const int rowb1 = (b * H + y1i) * H;
    const float4* __restrict__ q00 = f4 + (rowb0 + x0 ) * NCH4 + lane;
    const float4* __restrict__ q01 = f4 + (rowb0 + x1i) * NCH4 + lane;
    const float4* __restrict__ q10 = f4 + (rowb1 + x0 ) * NCH4 + lane;
    const float4* __restrict__ q11 = f4 + (rowb1 + x1i) * NCH4 + lane;

    // ---- 8 batched independent gathers (channels lane, lane+32) ----
    const float4 a00 = __ldg(q00);
    const float4 a01 = __ldg(q01);
    const float4 a10 = __ldg(q10);
    const float4 a11 = __ldg(q11);
    const float4 b00 = __ldg(q00 + 32);
    const float4 b01 = __ldg(q01 + 32);
    const float4 b10 = __ldg(q10 + 32);
    const float4 b11 = __ldg(q11 + 32);

    const float4 ra = lerp2(a00, a01, a10, a11, wx, wy);
    const float4 rb = lerp2(b00, b01, b10, b11, wx, wy);

    // out point block: pt * 64 float4
    float4* __restrict__ o = out + (long long)pt * NCH4 + lane;
    __stcs(o,      ra);
    __stcs(o + 32, rb);
}

extern "C" void kernel_launch(void* const* d_in, const int* in_sizes, int n_in,
                              void* d_out, int out_size)
{
    const float* boxes = (const float*)d_in[0];
    const float* p2    = (const float*)d_in[1];
    const float* p3    = (const float*)d_in[2];
    const float* p4    = (const float*)d_in[3];
    const float* p5    = (const float*)d_in[4];
    float4* out = (float4*)d_out;

    pyramid_roi_align_kernel<<<NPTS / 8, 256>>>(boxes, p2, p3, p4, p5, out);
}

// round 6
// speedup vs baseline: 1.1674x; 1.1550x over previous
#include <cuda_runtime.h>
#include <cstdint>

// PyramidROIAlign, single kernel, warp-per-pool-point.
//   boxes: (2, 1000, 4) f32; p2: (2, 256, 256, 256) f32 NHWC
//   out:   (2, 1000, 7, 7, 256) f32
//
// KEY FACT: roi_level = clip(round(log2(sqrt(max(h*w,1e-12))/0.21875)), 2, 5)
// For ANY normalized box h,w <= 1: sqrt(hw)/0.21875 <= 4.571 -> log2 <= 2.193
// -> round <= 2 -> clipped level == 2 ALWAYS. (Level 3 would need lvlf >= 2.5,
// i.e. sqrt(hw) >= 1.24 — impossible.) So only p2 (H=W=256) is ever sampled;
// p3/p4/p5 contribute nothing. Hardcoded below.
//
// 98000 points = 12250 blocks x 8 warps (exact, no tail).
// Warp-uniform param math in registers; each lane: 8 batched independent
// LDG.128 (4 corners x 2 channel halves), 2 lerps, 2 streaming STG.128.
// __launch_bounds__(256, 8) pins regs to 32 -> 8 blocks/SM (full occupancy).

#define BATCH   2
#define NROI    1000
#define POOLH   7
#define POOLW   7
#define NCH     256
#define NCH4    (NCH / 4)            // 64
#define POINTS  (POOLH * POOLW)      // 49
#define NPTS    (BATCH * NROI * POINTS)   // 98000
#define FH      256                  // p2 spatial size

__device__ __forceinline__ float4 lerp2(const float4 v00, const float4 v01,
                                        const float4 v10, const float4 v11,
                                        const float wx, const float wy)
{
    float4 r;
    float t, bo;
    t  = v00.x + wx * (v01.x - v00.x);
    bo = v10.x + wx * (v11.x - v10.x);
    r.x = t + wy * (bo - t);
    t  = v00.y + wx * (v01.y - v00.y);
    bo = v10.y + wx * (v11.y - v10.y);
    r.y = t + wy * (bo - t);
    t  = v00.z + wx * (v01.z - v00.z);
    bo = v10.z + wx * (v11.z - v10.z);
    r.z = t + wy * (bo - t);
    t  = v00.w + wx * (v01.w - v00.w);
    bo = v10.w + wx * (v11.w - v10.w);
    r.w = t + wy * (bo - t);
    return r;
}

__global__ __launch_bounds__(256, 8) void pyramid_roi_align_kernel(
    const float* __restrict__ boxes,
    const float* __restrict__ p2,
    float4* __restrict__ out)
{
    const int lane = threadIdx.x & 31;
    const int wrp  = threadIdx.x >> 5;
    const int pt   = blockIdx.x * 8 + wrp;    // 0..97999, exact

    // ---- warp-uniform param computation (registers only) ----
    const int roi = pt / POINTS;              // 0..1999 (IMAD magic div)
    const int ppt = pt - roi * POINTS;        // 0..48
    const int py  = ppt / POOLW;
    const int px  = ppt - py * POOLW;
    const int b   = roi >= NROI ? 1 : 0;

    const float4 bx = __ldg((const float4*)(boxes) + roi);
    const float y1 = bx.x, x1 = bx.y, y2 = bx.z, x2 = bx.w;
    const float h = y2 - y1;
    const float w = x2 - x1;

    // level == 2 always (see proof above): sample p2, H = W = 256.
    const float Hm1 = (float)(FH - 1);
    const float ty = (float)py * (1.0f / 6.0f);
    const float tx = (float)px * (1.0f / 6.0f);
    const float ysf = (y1 + h * ty) * Hm1;
    const float xsf = (x1 + w * tx) * Hm1;

    const float y0f = floorf(ysf);
    const float x0f = floorf(xsf);
    const float wy = ysf - y0f;   // weights from UNCLAMPED floor (matches ref)
    const float wx = xsf - x0f;

    const int y0  = min(max((int)y0f, 0), FH - 1);
    const int y1i = min(max((int)y0f + 1, 0), FH - 1);
    const int x0  = min(max((int)x0f, 0), FH - 1);
    const int x1i = min(max((int)x0f + 1, 0), FH - 1);

    // NHWC float4 view: p2_4[((b*256 + y)*256 + x)*64 + c]
    const float4* __restrict__ f4 = (const float4*)p2;
    const int rowb0 = (b * FH + y0)  * FH;
    const int rowb1 = (b * FH + y1i) * FH;
    const float4* __restrict__ q00 = f4 + (rowb0 + x0 ) * NCH4 + lane;
    const float4* __restrict__ q01 = f4 + (rowb0 + x1i) * NCH4 + lane;
    const float4* __restrict__ q10 = f4 + (rowb1 + x0 ) * NCH4 + lane;
    const float4* __restrict__ q11 = f4 + (rowb1 + x1i) * NCH4 + lane;

    // ---- 8 batched independent gathers (channels lane, lane+32) ----
    const float4 a00 = __ldg(q00);
    const float4 a01 = __ldg(q01);
    const float4 a10 = __ldg(q10);
    const float4 a11 = __ldg(q11);
    const float4 b00 = __ldg(q00 + 32);
    const float4 b01 = __ldg(q01 + 32);
    const float4 b10 = __ldg(q10 + 32);
    const float4 b11 = __ldg(q11 + 32);

    const float4 ra = lerp2(a00, a01, a10, a11, wx, wy);
    const float4 rb = lerp2(b00, b01, b10, b11, wx, wy);

    // out point block: pt * 64 float4
    float4* __restrict__ o = out + (long long)pt * NCH4 + lane;
    __stcs(o,      ra);
    __stcs(o + 32, rb);
}

extern "C" void kernel_launch(void* const* d_in, const int* in_sizes, int n_in,
                              void* d_out, int out_size)
{
    const float* boxes = (const float*)d_in[0];
    const float* p2    = (const float*)d_in[1];
    float4* out = (float4*)d_out;

    pyramid_roi_align_kernel<<<NPTS / 8, 256>>>(boxes, p2, out);
}